// round 1
// baseline (speedup 1.0000x reference)
#include <cuda_runtime.h>
#include <math.h>

#define NN 100000
#define EE 800000
#define DD 256
#define DH 128

// ------------------- device-global scratch (no cudaMalloc allowed) -------------------
__device__ float g_z [(size_t)NN * DD];   // state z
__device__ float g_tA[(size_t)NN * DD];   // RK4 stage input buffer A
__device__ float g_tB[(size_t)NN * DD];   // RK4 stage input buffer B
__device__ float g_k [(size_t)NN * DD];   // k accumulator
__device__ float g_alpha[NN];
__device__ float g_hb[NN * 2];            // h @ W_hh^T + b_ih + b_hh (per node, constant)
__device__ float g_M[DD * DD];            // (W*clip(d)) @ W^T - I
__device__ int   g_mflag;                 // nonzero if M != 0 (general fallback path)
__device__ int   g_rowptr[NN + 1];
__device__ int   g_cnt[NN];
__device__ unsigned long long g_edges[EE]; // packed: hi32 = val bits, lo32 = col

__device__ __forceinline__ float* buf_sel(int s) {
    return (s == 0) ? g_z : (s == 1) ? g_tA : g_tB;
}

// ------------------- init kernels -------------------
__global__ void init_z(const float* __restrict__ x) {
    int i = blockIdx.x * blockDim.x + threadIdx.x;   // over NN*DD (exact grid)
    int col = i & (DD - 1);
    int r   = i >> 8;
    g_z[i] = (col < DH) ? x[(size_t)r * DH + col] : 0.0f;
}

__global__ void init_small(const float* __restrict__ alpha0, const float* __restrict__ h,
                           const float* __restrict__ Whh, const float* __restrict__ bih,
                           const float* __restrict__ bhh) {
    int i = blockIdx.x * blockDim.x + threadIdx.x;
    if (i == 0) g_mflag = 0;
    if (i < NN) {
        g_alpha[i] = alpha0[i];
        float h0 = h[2 * i], h1 = h[2 * i + 1];
        g_hb[2 * i]     = h0 * Whh[0] + h1 * Whh[1] + bih[0] + bhh[0];
        g_hb[2 * i + 1] = h0 * Whh[2] + h1 * Whh[3] + bih[1] + bhh[1];
    }
}

__global__ void compute_M(const float* __restrict__ W, const float* __restrict__ dvec) {
    int i = blockIdx.x;   // 256 rows
    int j = threadIdx.x;  // 256 cols
    float s = 0.0f;
    for (int k = 0; k < DD; ++k) {
        float d = dvec[k];
        d = fminf(fmaxf(d, 0.0f), 1.0f);
        s += W[i * DD + k] * d * W[j * DD + k];
    }
    float m = s - ((i == j) ? 1.0f : 0.0f);
    g_M[i * DD + j] = m;
    if (m != 0.0f) atomicOr(&g_mflag, 1);
}

// ------------------- CSR build -------------------
__global__ void zero_cnt() {
    int i = blockIdx.x * blockDim.x + threadIdx.x;
    if (i < NN) g_cnt[i] = 0;
}

__global__ void count_k(const int* __restrict__ rows) {
    int i = blockIdx.x * blockDim.x + threadIdx.x;
    if (i < EE) atomicAdd(&g_cnt[rows[i]], 1);
}

__global__ void scan_k() {
    __shared__ int buf[1024];
    int carry = 0;
    for (int base = 0; base < NN; base += 1024) {
        int idx = base + (int)threadIdx.x;
        int v = (idx < NN) ? g_cnt[idx] : 0;
        buf[threadIdx.x] = v;
        __syncthreads();
        for (int off = 1; off < 1024; off <<= 1) {
            int tv = (threadIdx.x >= off) ? buf[threadIdx.x - off] : 0;
            __syncthreads();
            buf[threadIdx.x] += tv;
            __syncthreads();
        }
        if (idx < NN) g_rowptr[idx] = carry + buf[threadIdx.x] - v;  // exclusive
        carry += buf[1023];
        __syncthreads();
    }
    if (threadIdx.x == 0) g_rowptr[NN] = carry;
}

__global__ void scatter_k(const int* __restrict__ rows, const int* __restrict__ cols,
                          const float* __restrict__ vals) {
    int i = blockIdx.x * blockDim.x + threadIdx.x;
    if (i < EE) {
        int r = rows[i];
        int pos = g_rowptr[r] + atomicAdd(&g_cnt[r], 1);
        unsigned long long pk =
            ((unsigned long long)__float_as_uint(vals[i]) << 32) | (unsigned int)cols[i];
        g_edges[pos] = pk;
    }
}

// ------------------- fused ODE eval (one RK4 stage) -------------------
// mode 0: k = f;        zout = z + cnext*f
// mode 1: k += 2f;      zout = zbase + cnext*f
// mode 3: z  = zbase + dt6*(k + f);  optionally write first 128 cols to out
__global__ __launch_bounds__(256) void ode_eval(
    int zin_s, int zbase_s, int zout_s,
    const float* __restrict__ x, const float* __restrict__ Wih,
    float cnext, int mode, float dt6, float* __restrict__ out)
{
    const float* zin   = buf_sel(zin_s);
    const float* zbase = buf_sel(zbase_s);
    float*       zout  = buf_sel(zout_s);

    int r = blockIdx.x;
    int t = threadIdx.x;
    size_t ri = (size_t)r * DD + t;

    float zv = zin[ri];

    // gate dot products: a = tanh(z . Wih_row + hb)
    float d0 = zv * Wih[t];
    float d1 = zv * Wih[DD + t];
    #pragma unroll
    for (int off = 16; off; off >>= 1) {
        d0 += __shfl_down_sync(0xffffffffu, d0, off);
        d1 += __shfl_down_sync(0xffffffffu, d1, off);
    }
    __shared__ float s0[8], s1[8];
    __shared__ float s_alph;
    int w = t >> 5, l = t & 31;
    if (l == 0) { s0[w] = d0; s1[w] = d1; }
    __syncthreads();
    if (t == 0) {
        float a0 = 0.0f, a1 = 0.0f;
        #pragma unroll
        for (int i = 0; i < 8; ++i) { a0 += s0[i]; a1 += s1[i]; }
        a0 = tanhf(a0 + g_hb[2 * r]);
        a1 = tanhf(a1 + g_hb[2 * r + 1]);
        float al = g_alpha[r] * a0 + a1;
        g_alpha[r] = al;                    // stateful alpha carried eval-to-eval
        s_alph = 1.0f / (1.0f + expf(-al));
    }

    // SpMM row gather (runs before the sync; s_alph consumed after)
    int es = g_rowptr[r], ee = g_rowptr[r + 1];
    float az = 0.0f;
    #pragma unroll 4
    for (int i = es; i < ee; ++i) {
        unsigned long long pk = g_edges[i];
        int   c = (int)(unsigned int)(pk & 0xffffffffu);
        float v = __uint_as_float((unsigned int)(pk >> 32));
        az += v * zin[(size_t)c * DD + t];
    }
    __syncthreads();

    float f = s_alph * 0.5f * (az - zv) + ((t < DH) ? x[(size_t)r * DH + t] : 0.0f);

    if (g_mflag) {  // general fallback: f += z_row @ M  (never taken for given inputs: M == 0)
        const float* zr = zin + (size_t)r * DD;
        for (int j = 0; j < DD; ++j) f += zr[j] * g_M[j * DD + t];
    }

    if (mode == 0) {
        g_k[ri] = f;
        zout[ri] = zv + cnext * f;
    } else if (mode == 1) {
        g_k[ri] += 2.0f * f;
        zout[ri] = zbase[ri] + cnext * f;
    } else {  // mode 3: final stage of the RK4 step
        float zn = zbase[ri] + dt6 * (g_k[ri] + f);
        zout[ri] = zn;
        if (out != nullptr && t < DH) out[(size_t)r * DH + t] = zn;
    }
}

// ------------------- launch -------------------
extern "C" void kernel_launch(void* const* d_in, const int* in_sizes, int n_in,
                              void* d_out, int out_size) {
    const float* x      = (const float*)d_in[0];
    const int*   erows  = (const int*)  d_in[1];
    const int*   ecols  = (const int*)  d_in[2];
    const float* evals  = (const float*)d_in[3];
    const float* Wih    = (const float*)d_in[4];
    const float* Whh    = (const float*)d_in[5];
    const float* bih    = (const float*)d_in[6];
    const float* bhh    = (const float*)d_in[7];
    const float* h      = (const float*)d_in[8];
    const float* alpha0 = (const float*)d_in[9];
    const float* W      = (const float*)d_in[10];
    const float* dvec   = (const float*)d_in[11];
    float* out = (float*)d_out;

    // init state + constants
    init_z<<<NN, DD>>>(x);                                 // NN*DD threads exactly
    init_small<<<(NN + 255) / 256, 256>>>(alpha0, h, Whh, bih, bhh);
    compute_M<<<DD, DD>>>(W, dvec);

    // CSR build
    zero_cnt<<<(NN + 255) / 256, 256>>>();
    count_k<<<(EE + 255) / 256, 256>>>(erows);
    scan_k<<<1, 1024>>>();
    zero_cnt<<<(NN + 255) / 256, 256>>>();
    scatter_k<<<(EE + 255) / 256, 256>>>(erows, ecols, evals);

    const float dt  = 0.9f / 2.0f;   // 0.45
    const float hdt = 0.5f * dt;     // 0.225
    const float dt6 = dt / 6.0f;     // 0.075

    for (int s = 0; s < 2; ++s) {
        float* last_out = (s == 1) ? out : nullptr;
        // k1: zin=z(0)  -> tA(1)
        ode_eval<<<NN, DD>>>(0, 0, 1, x, Wih, hdt, 0, 0.0f, nullptr);
        // k2: zin=tA(1) -> tB(2)
        ode_eval<<<NN, DD>>>(1, 0, 2, x, Wih, hdt, 1, 0.0f, nullptr);
        // k3: zin=tB(2) -> tA(1)
        ode_eval<<<NN, DD>>>(2, 0, 1, x, Wih, dt, 1, 0.0f, nullptr);
        // k4: zin=tA(1) -> z(0) updated; last step also writes d_out
        ode_eval<<<NN, DD>>>(1, 0, 0, x, Wih, 0.0f, 3, dt6, last_out);
    }
}

// round 2
// speedup vs baseline: 2.3060x; 2.3060x over previous
#include <cuda_runtime.h>
#include <math.h>

#define NN 100000
#define EE 800000
#define DH 128
#define DD 256
#define NB2 (NN / 2)          // 50000 blocks, 2 rows each (fast path)
#define SCAN_B 1024
#define NBLK ((NN + SCAN_B - 1) / SCAN_B)   // 98

// ------------- device-global scratch (no cudaMalloc allowed) -------------
// fast-path buffers, layout [N,128]
__device__ float g_f0[(size_t)NN * DH];   // z
__device__ float g_f1[(size_t)NN * DH];   // t1 / t3
__device__ float g_f2[(size_t)NN * DH];   // t2
__device__ float g_f3[(size_t)NN * DH];   // acc = z + dt/6 k1 + dt/3 k2
// fallback (general M) buffers, layout [N,256]
__device__ float g_w0[(size_t)NN * DD];   // z
__device__ float g_w1[(size_t)NN * DD];   // tA
__device__ float g_w2[(size_t)NN * DD];   // tB
__device__ float g_wk[(size_t)NN * DD];   // k accumulator
__device__ float g_alpha[NN];
__device__ float g_hb[NN * 2];
__device__ float g_M[DD * DD];
__device__ int   g_mflag;
__device__ int   g_rowptr[NN + 1];
__device__ int   g_cnt[NN];
__device__ int   g_bsum[NBLK];
__device__ unsigned long long g_edges[EE]; // hi32 = val bits, lo32 = col

// ------------------- init kernels -------------------
__global__ void compute_M(const float* __restrict__ W, const float* __restrict__ dvec) {
    int i = blockIdx.x, j = threadIdx.x;
    if (i == 0 && j == 0) {}   // g_mflag zeroed below via atomic pattern: set here first
    float s = 0.0f;
    for (int k = 0; k < DD; ++k) {
        float d = fminf(fmaxf(dvec[k], 0.0f), 1.0f);
        s += W[i * DD + k] * d * W[j * DD + k];
    }
    float m = s - ((i == j) ? 1.0f : 0.0f);
    g_M[i * DD + j] = m;
    if (m != 0.0f) atomicOr(&g_mflag, 1);
}

__global__ void reset_flag() { g_mflag = 0; }

__global__ void init_z(const float* __restrict__ x) {
    int i = blockIdx.x * blockDim.x + threadIdx.x;  // grid covers NN*DH exactly
    if (!g_mflag) {
        g_f0[i] = x[i];
    } else {
        int r = i >> 7, c = i & 127;
        g_w0[(size_t)r * DD + c] = x[i];
        g_w0[(size_t)r * DD + DH + c] = 0.0f;
    }
}

__global__ void init_small(const float* __restrict__ alpha0, const float* __restrict__ h,
                           const float* __restrict__ Whh, const float* __restrict__ bih,
                           const float* __restrict__ bhh) {
    int i = blockIdx.x * blockDim.x + threadIdx.x;
    if (i < NN) {
        g_alpha[i] = alpha0[i];
        float h0 = h[2 * i], h1 = h[2 * i + 1];
        g_hb[2 * i]     = h0 * Whh[0] + h1 * Whh[1] + bih[0] + bhh[0];
        g_hb[2 * i + 1] = h0 * Whh[2] + h1 * Whh[3] + bih[1] + bhh[1];
    }
}

// ------------------- CSR build -------------------
__global__ void zero_cnt() {
    int i = blockIdx.x * blockDim.x + threadIdx.x;
    if (i < NN) g_cnt[i] = 0;
}
__global__ void count_k(const int* __restrict__ rows) {
    int i = blockIdx.x * blockDim.x + threadIdx.x;
    if (i < EE) atomicAdd(&g_cnt[rows[i]], 1);
}
__global__ void scan_local() {          // grid NBLK, block SCAN_B
    __shared__ int buf[SCAN_B];
    int idx = blockIdx.x * SCAN_B + (int)threadIdx.x;
    int v = (idx < NN) ? g_cnt[idx] : 0;
    buf[threadIdx.x] = v;
    __syncthreads();
    for (int off = 1; off < SCAN_B; off <<= 1) {
        int tv = (threadIdx.x >= off) ? buf[threadIdx.x - off] : 0;
        __syncthreads();
        buf[threadIdx.x] += tv;
        __syncthreads();
    }
    if (idx < NN) g_rowptr[idx] = buf[threadIdx.x] - v;       // local exclusive
    if (threadIdx.x == SCAN_B - 1) g_bsum[blockIdx.x] = buf[SCAN_B - 1];
}
__global__ void scan_bsum() {           // 1 block, 128 threads (NBLK <= 128)
    __shared__ int b[128];
    int v = ((int)threadIdx.x < NBLK) ? g_bsum[threadIdx.x] : 0;
    b[threadIdx.x] = v;
    __syncthreads();
    for (int off = 1; off < 128; off <<= 1) {
        int tv = (threadIdx.x >= off) ? b[threadIdx.x - off] : 0;
        __syncthreads();
        b[threadIdx.x] += tv;
        __syncthreads();
    }
    if ((int)threadIdx.x < NBLK) g_bsum[threadIdx.x] = b[threadIdx.x] - v;  // exclusive
    if (threadIdx.x == 127) g_rowptr[NN] = b[127];
}
__global__ void scan_add() {
    int i = blockIdx.x * blockDim.x + threadIdx.x;
    if (i < NN) g_rowptr[i] += g_bsum[i >> 10];
}
__global__ void scatter_k(const int* __restrict__ rows, const int* __restrict__ cols,
                          const float* __restrict__ vals) {
    int i = blockIdx.x * blockDim.x + threadIdx.x;
    if (i < EE) {
        int r = rows[i];
        int pos = g_rowptr[r] + atomicAdd(&g_cnt[r], 1);
        g_edges[pos] = ((unsigned long long)__float_as_uint(vals[i]) << 32)
                       | (unsigned int)cols[i];
    }
}

// ------------------- fused ODE eval (one RK4 stage) -------------------
// Fast path (M == 0): state is [N,128]; 2 rows per 256-thread block.
//   stage1: t1  = z + hdt*k1
//   stage2: t2  = z + hdt*k2 ; acc = z + dt/6*k1 + dt/3*k2, k1 = (t1-z)/hdt
//   stage3: t3  = z + dt*k3
//   stage4: z'  = acc + dt/3*k3 + dt/6*k4, k3 = (t3-z)/dt   (+ optional out)
// Fallback (M != 0): wide [N,256] with explicit k accumulator + dense z@M.
__global__ __launch_bounds__(256) void ode_eval(int stage,
    const float* __restrict__ x, const float* __restrict__ Wih,
    float* __restrict__ out)
{
    const float hdt = 0.225f, dt = 0.45f;
    __shared__ float s0[8], s1[8], s_al[2];
    int b = blockIdx.x, t = threadIdx.x;
    int w = t >> 5, l = t & 31;

    if (!g_mflag) {
        // ---------------- fast path ----------------
        int half = t >> 7, tl = t & 127;
        int r = 2 * b + half;
        const float* zin = (stage == 1) ? g_f0 : (stage == 2) ? g_f1
                         : (stage == 3) ? g_f2 : g_f1;
        size_t ri = (size_t)r * DH + tl;
        float zv = zin[ri];

        float d0 = zv * Wih[tl];
        float d1 = zv * Wih[DD + tl];
        #pragma unroll
        for (int off = 16; off; off >>= 1) {
            d0 += __shfl_down_sync(0xffffffffu, d0, off);
            d1 += __shfl_down_sync(0xffffffffu, d1, off);
        }
        if (l == 0) { s0[w] = d0; s1[w] = d1; }
        __syncthreads();
        if (tl == 0) {
            float a0 = 0.0f, a1 = 0.0f;
            #pragma unroll
            for (int i = 0; i < 4; ++i) { a0 += s0[half * 4 + i]; a1 += s1[half * 4 + i]; }
            a0 = tanhf(a0 + g_hb[2 * r]);
            a1 = tanhf(a1 + g_hb[2 * r + 1]);
            float al = g_alpha[r] * a0 + a1;
            g_alpha[r] = al;
            s_al[half] = 1.0f / (1.0f + expf(-al));
        }
        // gather (independent of s_al; overlaps the leader's special math)
        int es = g_rowptr[r], ee = g_rowptr[r + 1];
        float az = 0.0f;
        #pragma unroll 4
        for (int i = es; i < ee; ++i) {
            unsigned long long pk = g_edges[i];
            int   c = (int)(unsigned int)(pk & 0xffffffffu);
            float v = __uint_as_float((unsigned int)(pk >> 32));
            az += v * zin[(size_t)c * DH + tl];
        }
        __syncthreads();
        float f = s_al[half] * 0.5f * (az - zv) + x[ri];

        if (stage == 1) {
            g_f1[ri] = zv + hdt * f;                 // zin == z here
        } else if (stage == 2) {
            float z0 = g_f0[ri];
            float k1 = (zv - z0) * (1.0f / 0.225f);  // zin == t1
            g_f2[ri] = z0 + hdt * f;
            g_f3[ri] = z0 + (dt / 6.0f) * k1 + (dt / 3.0f) * f;
        } else if (stage == 3) {
            float z0 = g_f0[ri];
            g_f1[ri] = z0 + dt * f;
        } else {
            float z0 = g_f0[ri];
            float k3 = (zv - z0) * (1.0f / 0.45f);   // zin == t3
            float zn = g_f3[ri] + (dt / 3.0f) * k3 + (dt / 6.0f) * f;
            g_f0[ri] = zn;
            if (out != nullptr) out[ri] = zn;
        }
    } else {
        // ---------------- general fallback (never taken for given inputs) ----------------
        const float dt6 = dt / 6.0f;
        for (int rr = 0; rr < 2; ++rr) {
            int r = 2 * b + rr;
            const float* zin = (stage == 1) ? g_w0 : (stage == 2) ? g_w1
                             : (stage == 3) ? g_w2 : g_w1;
            size_t ri = (size_t)r * DD + t;
            float zv = zin[ri];
            float d0 = zv * Wih[t];
            float d1 = zv * Wih[DD + t];
            #pragma unroll
            for (int off = 16; off; off >>= 1) {
                d0 += __shfl_down_sync(0xffffffffu, d0, off);
                d1 += __shfl_down_sync(0xffffffffu, d1, off);
            }
            if (l == 0) { s0[w] = d0; s1[w] = d1; }
            __syncthreads();
            if (t == 0) {
                float a0 = 0.0f, a1 = 0.0f;
                #pragma unroll
                for (int i = 0; i < 8; ++i) { a0 += s0[i]; a1 += s1[i]; }
                a0 = tanhf(a0 + g_hb[2 * r]);
                a1 = tanhf(a1 + g_hb[2 * r + 1]);
                float al = g_alpha[r] * a0 + a1;
                g_alpha[r] = al;
                s_al[0] = 1.0f / (1.0f + expf(-al));
            }
            int es = g_rowptr[r], ee = g_rowptr[r + 1];
            float az = 0.0f;
            for (int i = es; i < ee; ++i) {
                unsigned long long pk = g_edges[i];
                int   c = (int)(unsigned int)(pk & 0xffffffffu);
                float v = __uint_as_float((unsigned int)(pk >> 32));
                az += v * zin[(size_t)c * DD + t];
            }
            __syncthreads();
            float f = s_al[0] * 0.5f * (az - zv) + ((t < DH) ? x[(size_t)r * DH + t] : 0.0f);
            const float* zr = zin + (size_t)r * DD;
            for (int j = 0; j < DD; ++j) f += zr[j] * g_M[j * DD + t];

            if (stage == 1) { g_wk[ri] = f;          g_w1[ri] = zv + hdt * f; }
            else if (stage == 2) { g_wk[ri] += 2.0f * f; g_w2[ri] = g_w0[ri] + hdt * f; }
            else if (stage == 3) { g_wk[ri] += 2.0f * f; g_w1[ri] = g_w0[ri] + dt * f; }
            else {
                float zn = g_w0[ri] + dt6 * (g_wk[ri] + f);
                g_w0[ri] = zn;
                if (out != nullptr && t < DH) out[(size_t)r * DH + t] = zn;
            }
            __syncthreads();
        }
    }
}

// ------------------- launch -------------------
extern "C" void kernel_launch(void* const* d_in, const int* in_sizes, int n_in,
                              void* d_out, int out_size) {
    const float* x      = (const float*)d_in[0];
    const int*   erows  = (const int*)  d_in[1];
    const int*   ecols  = (const int*)  d_in[2];
    const float* evals  = (const float*)d_in[3];
    const float* Wih    = (const float*)d_in[4];
    const float* Whh    = (const float*)d_in[5];
    const float* bih    = (const float*)d_in[6];
    const float* bhh    = (const float*)d_in[7];
    const float* h      = (const float*)d_in[8];
    const float* alpha0 = (const float*)d_in[9];
    const float* W      = (const float*)d_in[10];
    const float* dvec   = (const float*)d_in[11];
    float* out = (float*)d_out;

    reset_flag<<<1, 1>>>();
    compute_M<<<DD, DD>>>(W, dvec);
    init_z<<<(NN * DH) / 256, 256>>>(x);
    init_small<<<(NN + 255) / 256, 256>>>(alpha0, h, Whh, bih, bhh);

    zero_cnt<<<(NN + 255) / 256, 256>>>();
    count_k<<<(EE + 255) / 256, 256>>>(erows);
    scan_local<<<NBLK, SCAN_B>>>();
    scan_bsum<<<1, 128>>>();
    scan_add<<<(NN + 255) / 256, 256>>>();
    zero_cnt<<<(NN + 255) / 256, 256>>>();
    scatter_k<<<(EE + 255) / 256, 256>>>(erows, ecols, evals);

    for (int s = 0; s < 2; ++s) {
        float* last_out = (s == 1) ? out : nullptr;
        ode_eval<<<NB2, 256>>>(1, x, Wih, nullptr);
        ode_eval<<<NB2, 256>>>(2, x, Wih, nullptr);
        ode_eval<<<NB2, 256>>>(3, x, Wih, nullptr);
        ode_eval<<<NB2, 256>>>(4, x, Wih, last_out);
    }
}

// round 3
// speedup vs baseline: 3.3202x; 1.4398x over previous
#include <cuda_runtime.h>
#include <cuda_fp16.h>
#include <math.h>

#define NN 100000
#define EE 800000
#define DH 128
#define DHH 64            // half2 / float2 columns
#define DD 256
#define RPB 4             // rows per block (fast path)
#define NB4 (NN / RPB)    // 25000
#define SCAN_B 1024
#define NBLK ((NN + SCAN_B - 1) / SCAN_B)   // 98

// ------------- device-global scratch (no cudaMalloc allowed) -------------
// fast path
__device__ float  g_f0 [(size_t)NN * DH];   // z (fp32 carried state)
__device__ float  g_acc[(size_t)NN * DH];   // z + dt/6 k1 + dt/3 k2
__device__ __half g_h0 [(size_t)NN * DH];   // fp16 mirror of z
__device__ __half g_t1 [(size_t)NN * DH];   // t1 / t3 (fp16 only)
__device__ __half g_t2 [(size_t)NN * DH];   // t2 (fp16 only)
__device__ __half g_kh [(size_t)NN * DH];   // k1 / k3 (fp16)
// fallback (general M) buffers, layout [N,256]
__device__ float g_w0[(size_t)NN * DD];
__device__ float g_w1[(size_t)NN * DD];
__device__ float g_w2[(size_t)NN * DD];
__device__ float g_wk[(size_t)NN * DD];
__device__ float g_alpha[NN];
__device__ float g_hb[NN * 2];
__device__ float g_M[DD * DD];
__device__ int   g_mflag;
__device__ int   g_rowptr[NN + 1];
__device__ int   g_cnt[NN];
__device__ int   g_bsum[NBLK];
__device__ unsigned long long g_edges[EE]; // hi32 = val bits, lo32 = col

// ------------------- setup kernels -------------------
__global__ void reset_all() {                       // zero cnt + flag
    int i = blockIdx.x * blockDim.x + threadIdx.x;
    if (i == 0) g_mflag = 0;
    if (i < NN) g_cnt[i] = 0;
}

// blocks [0,256): compute M row blockIdx; blocks [256,647): init alpha/hb
__global__ void computeM_small(const float* __restrict__ W, const float* __restrict__ dvec,
                               const float* __restrict__ alpha0, const float* __restrict__ h,
                               const float* __restrict__ Whh, const float* __restrict__ bih,
                               const float* __restrict__ bhh) {
    if (blockIdx.x < DD) {
        int i = blockIdx.x, j = threadIdx.x;
        float s = 0.0f;
        for (int k = 0; k < DD; ++k) {
            float d = fminf(fmaxf(dvec[k], 0.0f), 1.0f);
            s += W[i * DD + k] * d * W[j * DD + k];
        }
        float m = s - ((i == j) ? 1.0f : 0.0f);
        g_M[i * DD + j] = m;
        if (m != 0.0f) atomicOr(&g_mflag, 1);
    } else {
        int i = (blockIdx.x - DD) * blockDim.x + threadIdx.x;
        if (i < NN) {
            g_alpha[i] = alpha0[i];
            float h0 = h[2 * i], h1 = h[2 * i + 1];
            g_hb[2 * i]     = h0 * Whh[0] + h1 * Whh[1] + bih[0] + bhh[0];
            g_hb[2 * i + 1] = h0 * Whh[2] + h1 * Whh[3] + bih[1] + bhh[1];
        }
    }
}

__global__ void count_k(const int* __restrict__ rows) {
    int i = blockIdx.x * blockDim.x + threadIdx.x;
    if (i < EE) atomicAdd(&g_cnt[rows[i]], 1);
}

// blocks [0,NBLK): local scan of counts; blocks [NBLK,...): init z buffers
__global__ void scan_initz(const float* __restrict__ x) {
    if (blockIdx.x < NBLK) {
        __shared__ int buf[SCAN_B];
        int idx = blockIdx.x * SCAN_B + (int)threadIdx.x;
        int v = (idx < NN) ? g_cnt[idx] : 0;
        buf[threadIdx.x] = v;
        __syncthreads();
        for (int off = 1; off < SCAN_B; off <<= 1) {
            int tv = (threadIdx.x >= off) ? buf[threadIdx.x - off] : 0;
            __syncthreads();
            buf[threadIdx.x] += tv;
            __syncthreads();
        }
        if (idx < NN) g_rowptr[idx] = buf[threadIdx.x] - v;       // local exclusive
        if (threadIdx.x == SCAN_B - 1) g_bsum[blockIdx.x] = buf[SCAN_B - 1];
    } else {
        int i = (blockIdx.x - NBLK) * SCAN_B + (int)threadIdx.x;  // over NN*DH
        if (i < NN * DH) {
            float v = x[i];
            if (!g_mflag) {
                g_f0[i] = v;
                g_h0[i] = __float2half(v);
            } else {
                int r = i >> 7, c = i & 127;
                g_w0[(size_t)r * DD + c] = v;
                g_w0[(size_t)r * DD + DH + c] = 0.0f;
            }
        }
    }
}

__global__ void scan_bsum() {           // 1 block, 128 threads (NBLK <= 128)
    __shared__ int b[128];
    int v = ((int)threadIdx.x < NBLK) ? g_bsum[threadIdx.x] : 0;
    b[threadIdx.x] = v;
    __syncthreads();
    for (int off = 1; off < 128; off <<= 1) {
        int tv = (threadIdx.x >= off) ? b[threadIdx.x - off] : 0;
        __syncthreads();
        b[threadIdx.x] += tv;
        __syncthreads();
    }
    if ((int)threadIdx.x < NBLK) g_bsum[threadIdx.x] = b[threadIdx.x] - v;  // exclusive
    if (threadIdx.x == 127) g_rowptr[NN] = b[127];
}

__global__ void scan_add_zero() {
    int i = blockIdx.x * blockDim.x + threadIdx.x;
    if (i < NN) {
        g_rowptr[i] += g_bsum[i >> 10];
        g_cnt[i] = 0;
    }
}

__global__ void scatter_k(const int* __restrict__ rows, const int* __restrict__ cols,
                          const float* __restrict__ vals) {
    int i = blockIdx.x * blockDim.x + threadIdx.x;
    if (i < EE) {
        int r = rows[i];
        int pos = g_rowptr[r] + atomicAdd(&g_cnt[r], 1);
        g_edges[pos] = ((unsigned long long)__float_as_uint(vals[i]) << 32)
                       | (unsigned int)cols[i];
    }
}

// ------------------- fused ODE eval (one RK4 stage) -------------------
// Fast path: 4 rows per 256-thread block, 64 threads/row, half2 lanes.
//   s1: gather h0 -> f1;  t1 = z + hdt f1 (fp16), kh = f1 (fp16)
//   s2: gather t1 -> f2;  t2 = z + hdt f2 (fp16), acc = z + dt/6 kh + dt/3 f2
//   s3: gather t2 -> f3;  t1 = z + dt f3 (fp16),  kh = f3 (fp16)
//   s4: gather t1 -> f4;  z' = acc + dt/3 kh + dt/6 f4 (fp32 + fp16 mirror, + out)
__global__ __launch_bounds__(256) void ode_eval(int stage,
    const float* __restrict__ x, const float* __restrict__ Wih,
    float* __restrict__ out)
{
    const float hdt = 0.225f, dt = 0.45f, dt3 = 0.15f, dt6 = 0.075f;
    __shared__ float s0[8], s1v[8], s_al[RPB];
    int t = threadIdx.x;

    if (!g_mflag) {
        int rr = t >> 6, tl = t & 63;
        int r = blockIdx.x * RPB + rr;
        const __half2* zin = (stage == 1) ? (const __half2*)g_h0
                           : (stage == 3) ? (const __half2*)g_t2
                           : (const __half2*)g_t1;          // stages 2 & 4
        size_t ri = (size_t)r * DHH + tl;

        float2 zv;
        if (stage == 1) zv = ((const float2*)g_f0)[ri];
        else            zv = __half22float2(zin[ri]);

        // gate dots
        float2 w0 = ((const float2*)Wih)[tl];
        float2 w1 = ((const float2*)Wih)[DHH * 2 + tl];     // second row at +256 floats
        float d0 = zv.x * w0.x + zv.y * w0.y;
        float d1 = zv.x * w1.x + zv.y * w1.y;
        #pragma unroll
        for (int off = 16; off; off >>= 1) {
            d0 += __shfl_down_sync(0xffffffffu, d0, off);
            d1 += __shfl_down_sync(0xffffffffu, d1, off);
        }
        int w = t >> 5, l = t & 31;
        if (l == 0) { s0[w] = d0; s1v[w] = d1; }
        __syncthreads();
        if (tl == 0) {
            float a0 = tanhf(s0[2 * rr] + s0[2 * rr + 1] + g_hb[2 * r]);
            float a1 = tanhf(s1v[2 * rr] + s1v[2 * rr + 1] + g_hb[2 * r + 1]);
            float al = g_alpha[r] * a0 + a1;
            g_alpha[r] = al;
            s_al[rr] = 1.0f / (1.0f + expf(-al));
        }

        // SpMM gather from fp16 mirror (overlaps leader's special math)
        int es = g_rowptr[r], ee = g_rowptr[r + 1];
        float ax = 0.0f, ay = 0.0f;
        #pragma unroll 4
        for (int i = es; i < ee; ++i) {
            unsigned long long pk = g_edges[i];
            int   c = (int)(unsigned int)(pk & 0xffffffffu);
            float v = __uint_as_float((unsigned int)(pk >> 32));
            float2 zf = __half22float2(zin[(size_t)c * DHH + tl]);
            ax += v * zf.x;
            ay += v * zf.y;
        }
        __syncthreads();

        float al = s_al[rr];
        float2 x2 = ((const float2*)x)[ri];
        float fx = al * 0.5f * (ax - zv.x) + x2.x;
        float fy = al * 0.5f * (ay - zv.y) + x2.y;

        if (stage == 1) {
            ((__half2*)g_t1)[ri] = __floats2half2_rn(zv.x + hdt * fx, zv.y + hdt * fy);
            ((__half2*)g_kh)[ri] = __floats2half2_rn(fx, fy);
        } else if (stage == 2) {
            float2 z0 = ((const float2*)g_f0)[ri];
            float2 k1 = __half22float2(((const __half2*)g_kh)[ri]);
            ((__half2*)g_t2)[ri] = __floats2half2_rn(z0.x + hdt * fx, z0.y + hdt * fy);
            float2 ac;
            ac.x = z0.x + dt6 * k1.x + dt3 * fx;
            ac.y = z0.y + dt6 * k1.y + dt3 * fy;
            ((float2*)g_acc)[ri] = ac;
        } else if (stage == 3) {
            float2 z0 = ((const float2*)g_f0)[ri];
            ((__half2*)g_t1)[ri] = __floats2half2_rn(z0.x + dt * fx, z0.y + dt * fy);
            ((__half2*)g_kh)[ri] = __floats2half2_rn(fx, fy);
        } else {
            float2 ac = ((const float2*)g_acc)[ri];
            float2 k3 = __half22float2(((const __half2*)g_kh)[ri]);
            float2 zn;
            zn.x = ac.x + dt3 * k3.x + dt6 * fx;
            zn.y = ac.y + dt3 * k3.y + dt6 * fy;
            ((float2*)g_f0)[ri] = zn;
            ((__half2*)g_h0)[ri] = __floats2half2_rn(zn.x, zn.y);
            if (out != nullptr) ((float2*)out)[ri] = zn;
        }
    } else {
        // -------- general fallback (never taken for given inputs) --------
        int w = t >> 5, l = t & 31;
        for (int rr = 0; rr < RPB; ++rr) {
            int r = blockIdx.x * RPB + rr;
            const float* zin = (stage == 1) ? g_w0 : (stage == 2) ? g_w1
                             : (stage == 3) ? g_w2 : g_w1;
            size_t ri = (size_t)r * DD + t;
            float zv = zin[ri];
            float d0 = zv * Wih[t];
            float d1 = zv * Wih[DD + t];
            #pragma unroll
            for (int off = 16; off; off >>= 1) {
                d0 += __shfl_down_sync(0xffffffffu, d0, off);
                d1 += __shfl_down_sync(0xffffffffu, d1, off);
            }
            if (l == 0) { s0[w] = d0; s1v[w] = d1; }
            __syncthreads();
            if (t == 0) {
                float a0 = 0.0f, a1 = 0.0f;
                #pragma unroll
                for (int i = 0; i < 8; ++i) { a0 += s0[i]; a1 += s1v[i]; }
                a0 = tanhf(a0 + g_hb[2 * r]);
                a1 = tanhf(a1 + g_hb[2 * r + 1]);
                float al = g_alpha[r] * a0 + a1;
                g_alpha[r] = al;
                s_al[0] = 1.0f / (1.0f + expf(-al));
            }
            int es = g_rowptr[r], ee = g_rowptr[r + 1];
            float az = 0.0f;
            for (int i = es; i < ee; ++i) {
                unsigned long long pk = g_edges[i];
                int   c = (int)(unsigned int)(pk & 0xffffffffu);
                float v = __uint_as_float((unsigned int)(pk >> 32));
                az += v * zin[(size_t)c * DD + t];
            }
            __syncthreads();
            float f = s_al[0] * 0.5f * (az - zv) + ((t < DH) ? x[(size_t)r * DH + t] : 0.0f);
            const float* zr = zin + (size_t)r * DD;
            for (int j = 0; j < DD; ++j) f += zr[j] * g_M[j * DD + t];

            if (stage == 1)      { g_wk[ri] = f;          g_w1[ri] = zv + hdt * f; }
            else if (stage == 2) { g_wk[ri] += 2.0f * f;  g_w2[ri] = g_w0[ri] + hdt * f; }
            else if (stage == 3) { g_wk[ri] += 2.0f * f;  g_w1[ri] = g_w0[ri] + dt * f; }
            else {
                float zn = g_w0[ri] + dt6 * (g_wk[ri] + f);
                g_w0[ri] = zn;
                if (out != nullptr && t < DH) out[(size_t)r * DH + t] = zn;
            }
            __syncthreads();
        }
    }
}

// ------------------- launch -------------------
extern "C" void kernel_launch(void* const* d_in, const int* in_sizes, int n_in,
                              void* d_out, int out_size) {
    const float* x      = (const float*)d_in[0];
    const int*   erows  = (const int*)  d_in[1];
    const int*   ecols  = (const int*)  d_in[2];
    const float* evals  = (const float*)d_in[3];
    const float* Wih    = (const float*)d_in[4];
    const float* Whh    = (const float*)d_in[5];
    const float* bih    = (const float*)d_in[6];
    const float* bhh    = (const float*)d_in[7];
    const float* h      = (const float*)d_in[8];
    const float* alpha0 = (const float*)d_in[9];
    const float* W      = (const float*)d_in[10];
    const float* dvec   = (const float*)d_in[11];
    float* out = (float*)d_out;

    reset_all<<<(NN + 255) / 256, 256>>>();
    computeM_small<<<DD + (NN + 255) / 256, 256>>>(W, dvec, alpha0, h, Whh, bih, bhh);
    count_k<<<(EE + 255) / 256, 256>>>(erows);
    scan_initz<<<NBLK + (NN * DH + SCAN_B - 1) / SCAN_B, SCAN_B>>>(x);
    scan_bsum<<<1, 128>>>();
    scan_add_zero<<<(NN + 255) / 256, 256>>>();
    scatter_k<<<(EE + 255) / 256, 256>>>(erows, ecols, evals);

    for (int s = 0; s < 2; ++s) {
        float* last_out = (s == 1) ? out : nullptr;
        ode_eval<<<NB4, 256>>>(1, x, Wih, nullptr);
        ode_eval<<<NB4, 256>>>(2, x, Wih, nullptr);
        ode_eval<<<NB4, 256>>>(3, x, Wih, nullptr);
        ode_eval<<<NB4, 256>>>(4, x, Wih, last_out);
    }
}

// round 5
// speedup vs baseline: 4.4403x; 1.3374x over previous
#include <cuda_runtime.h>
#include <cuda_fp16.h>
#include <math.h>

#define NN 100000
#define EE 800000
#define DH 128
#define DD 256
#define RPB 8             // rows per block = warps per block (fast path)
#define NB8 (NN / RPB)    // 12500
#define SCAN_B 1024
#define NBLK ((NN + SCAN_B - 1) / SCAN_B)   // 98

// bit-cast helpers (no intrinsic dependency)
__device__ __forceinline__ unsigned int h2u(__half2 h) {
    return *reinterpret_cast<unsigned int*>(&h);
}
__device__ __forceinline__ __half2 u2h(unsigned int u) {
    return *reinterpret_cast<__half2*>(&u);
}

// ------------- device-global scratch (no cudaMalloc allowed) -------------
// fast path
__device__ float  g_f0 [(size_t)NN * DH];   // z (fp32 carried state)
__device__ float  g_acc[(size_t)NN * DH];   // z + dt/6 k1 + dt/3 k2
__device__ __half g_h0 [(size_t)NN * DH];   // fp16 mirror of z
__device__ __half g_t1 [(size_t)NN * DH];   // t1 / t3 (fp16 only)
__device__ __half g_t2 [(size_t)NN * DH];   // t2 (fp16 only)
__device__ __half g_kh [(size_t)NN * DH];   // k1 / k3 (fp16)
// fallback (general M) buffers, layout [N,256]
__device__ float g_w0[(size_t)NN * DD];
__device__ float g_w1[(size_t)NN * DD];
__device__ float g_w2[(size_t)NN * DD];
__device__ float g_wk[(size_t)NN * DD];
__device__ float g_alpha[NN];
__device__ float g_hb[NN * 2];
__device__ float g_M[DD * DD];
__device__ int   g_mflag;
__device__ int   g_rowptr[NN + 1];
__device__ int   g_cnt[NN];
__device__ int   g_bsum[NBLK];
__device__ unsigned long long g_edges[EE]; // hi32 = val bits, lo32 = col

// ------------------- setup kernels -------------------
__global__ void reset_all() {
    int i = blockIdx.x * blockDim.x + threadIdx.x;
    if (i == 0) g_mflag = 0;
    if (i < NN) g_cnt[i] = 0;
}

__global__ void computeM_small(const float* __restrict__ W, const float* __restrict__ dvec,
                               const float* __restrict__ alpha0, const float* __restrict__ h,
                               const float* __restrict__ Whh, const float* __restrict__ bih,
                               const float* __restrict__ bhh) {
    if (blockIdx.x < DD) {
        int i = blockIdx.x, j = threadIdx.x;
        float s = 0.0f;
        for (int k = 0; k < DD; ++k) {
            float d = fminf(fmaxf(dvec[k], 0.0f), 1.0f);
            s += W[i * DD + k] * d * W[j * DD + k];
        }
        float m = s - ((i == j) ? 1.0f : 0.0f);
        g_M[i * DD + j] = m;
        if (m != 0.0f) atomicOr(&g_mflag, 1);
    } else {
        int i = (blockIdx.x - DD) * blockDim.x + threadIdx.x;
        if (i < NN) {
            g_alpha[i] = alpha0[i];
            float h0 = h[2 * i], h1 = h[2 * i + 1];
            g_hb[2 * i]     = h0 * Whh[0] + h1 * Whh[1] + bih[0] + bhh[0];
            g_hb[2 * i + 1] = h0 * Whh[2] + h1 * Whh[3] + bih[1] + bhh[1];
        }
    }
}

__global__ void count_k(const int* __restrict__ rows) {
    int i = blockIdx.x * blockDim.x + threadIdx.x;
    if (i < EE) atomicAdd(&g_cnt[rows[i]], 1);
}

// blocks [0,NBLK): local scan; blocks [NBLK, ...): vectorized z init
__global__ void scan_initz(const float* __restrict__ x) {
    if (blockIdx.x < NBLK) {
        __shared__ int buf[SCAN_B];
        int idx = blockIdx.x * SCAN_B + (int)threadIdx.x;
        int v = (idx < NN) ? g_cnt[idx] : 0;
        buf[threadIdx.x] = v;
        __syncthreads();
        for (int off = 1; off < SCAN_B; off <<= 1) {
            int tv = (threadIdx.x >= off) ? buf[threadIdx.x - off] : 0;
            __syncthreads();
            buf[threadIdx.x] += tv;
            __syncthreads();
        }
        if (idx < NN) g_rowptr[idx] = buf[threadIdx.x] - v;       // local exclusive
        if (threadIdx.x == SCAN_B - 1) g_bsum[blockIdx.x] = buf[SCAN_B - 1];
    } else {
        int i = (blockIdx.x - NBLK) * SCAN_B + (int)threadIdx.x;  // over NN*DH/4
        if (i < NN * DH / 4) {
            float4 v = ((const float4*)x)[i];
            if (!g_mflag) {
                ((float4*)g_f0)[i] = v;
                uint2 hh;
                hh.x = h2u(__floats2half2_rn(v.x, v.y));
                hh.y = h2u(__floats2half2_rn(v.z, v.w));
                ((uint2*)g_h0)[i] = hh;
            } else {
                int r = i >> 5, c = (i & 31) * 4;
                float4* w = (float4*)(g_w0 + (size_t)r * DD);
                w[c / 4] = v;
                w[(DH + c) / 4] = make_float4(0.f, 0.f, 0.f, 0.f);
            }
        }
    }
}

__global__ void scan_bsum() {           // 1 block, 128 threads (NBLK <= 128)
    __shared__ int b[128];
    int v = ((int)threadIdx.x < NBLK) ? g_bsum[threadIdx.x] : 0;
    b[threadIdx.x] = v;
    __syncthreads();
    for (int off = 1; off < 128; off <<= 1) {
        int tv = (threadIdx.x >= off) ? b[threadIdx.x - off] : 0;
        __syncthreads();
        b[threadIdx.x] += tv;
        __syncthreads();
    }
    if ((int)threadIdx.x < NBLK) g_bsum[threadIdx.x] = b[threadIdx.x] - v;
    if (threadIdx.x == 127) g_rowptr[NN] = b[127];
}

__global__ void scan_add_zero() {
    int i = blockIdx.x * blockDim.x + threadIdx.x;
    if (i < NN) {
        g_rowptr[i] += g_bsum[i >> 10];
        g_cnt[i] = 0;
    }
}

__global__ void scatter_k(const int* __restrict__ rows, const int* __restrict__ cols,
                          const float* __restrict__ vals) {
    int i = blockIdx.x * blockDim.x + threadIdx.x;
    if (i < EE) {
        int r = rows[i];
        int pos = g_rowptr[r] + atomicAdd(&g_cnt[r], 1);
        g_edges[pos] = ((unsigned long long)__float_as_uint(vals[i]) << 32)
                       | (unsigned int)cols[i];
    }
}

// gather one edge into a 4-wide accumulator (lane covers cols 4*lane..4*lane+3)
__device__ __forceinline__ void edge_acc(const __half* zin, unsigned long long pk,
                                         int lane, float4& az) {
    int   c = (int)(unsigned int)(pk & 0xffffffffu);
    float v = __uint_as_float((unsigned int)(pk >> 32));
    uint2 hv = ((const uint2*)(zin + (size_t)c * DH))[lane];
    float2 a = __half22float2(u2h(hv.x));
    float2 b = __half22float2(u2h(hv.y));
    az.x += v * a.x; az.y += v * a.y; az.z += v * b.x; az.w += v * b.y;
}

// ------------------- fused ODE eval (one RK4 stage) -------------------
// Fast path: warp-per-row, 32 lanes x 4 cols, no shared memory / block sync.
__global__ __launch_bounds__(256) void ode_eval(int stage,
    const float* __restrict__ x, const float* __restrict__ Wih,
    float* __restrict__ out)
{
    const float hdt = 0.225f, dt = 0.45f, dt3 = 0.15f, dt6 = 0.075f;
    int t = threadIdx.x;

    if (!g_mflag) {
        int wrp = t >> 5, lane = t & 31;
        int r = blockIdx.x * RPB + wrp;
        const __half* zin = (stage == 1) ? g_h0 : (stage == 3) ? g_t2 : g_t1;
        size_t r4 = (size_t)r * (DH / 4) + lane;     // float4/uint2 index

        float4 zv;
        if (stage == 1) zv = ((const float4*)g_f0)[r4];
        else {
            uint2 hv = ((const uint2*)zin)[r4];
            float2 a = __half22float2(u2h(hv.x));
            float2 b = __half22float2(u2h(hv.y));
            zv = make_float4(a.x, a.y, b.x, b.y);
        }

        // gate dots -> all-lanes butterfly reduction
        float4 w0 = ((const float4*)Wih)[lane];
        float4 w1 = ((const float4*)(Wih + DD))[lane];
        float d0 = zv.x * w0.x + zv.y * w0.y + zv.z * w0.z + zv.w * w0.w;
        float d1 = zv.x * w1.x + zv.y * w1.y + zv.z * w1.z + zv.w * w1.w;
        #pragma unroll
        for (int off = 16; off; off >>= 1) {
            d0 += __shfl_xor_sync(0xffffffffu, d0, off);
            d1 += __shfl_xor_sync(0xffffffffu, d1, off);
        }
        float a0 = tanhf(d0 + g_hb[2 * r]);
        float a1 = tanhf(d1 + g_hb[2 * r + 1]);
        float al = g_alpha[r] * a0 + a1;          // all lanes redundantly
        if (lane == 0) g_alpha[r] = al;
        al = 1.0f / (1.0f + expf(-al));

        // SpMM gather, 4-deep software pipeline
        int es = g_rowptr[r], ee = g_rowptr[r + 1];
        float4 az = make_float4(0.f, 0.f, 0.f, 0.f);
        int i = es;
        for (; i + 4 <= ee; i += 4) {
            unsigned long long p0 = g_edges[i],     p1 = g_edges[i + 1];
            unsigned long long p2 = g_edges[i + 2], p3 = g_edges[i + 3];
            edge_acc(zin, p0, lane, az);
            edge_acc(zin, p1, lane, az);
            edge_acc(zin, p2, lane, az);
            edge_acc(zin, p3, lane, az);
        }
        for (; i < ee; ++i) edge_acc(zin, g_edges[i], lane, az);

        float4 x4 = ((const float4*)x)[r4];
        float4 f;
        f.x = al * 0.5f * (az.x - zv.x) + x4.x;
        f.y = al * 0.5f * (az.y - zv.y) + x4.y;
        f.z = al * 0.5f * (az.z - zv.z) + x4.z;
        f.w = al * 0.5f * (az.w - zv.w) + x4.w;

        if (stage == 1) {
            uint2 th, kh;
            th.x = h2u(__floats2half2_rn(zv.x + hdt * f.x, zv.y + hdt * f.y));
            th.y = h2u(__floats2half2_rn(zv.z + hdt * f.z, zv.w + hdt * f.w));
            kh.x = h2u(__floats2half2_rn(f.x, f.y));
            kh.y = h2u(__floats2half2_rn(f.z, f.w));
            ((uint2*)g_t1)[r4] = th;
            ((uint2*)g_kh)[r4] = kh;
        } else if (stage == 2) {
            float4 z0 = ((const float4*)g_f0)[r4];
            uint2 khv = ((const uint2*)g_kh)[r4];
            float2 k1a = __half22float2(u2h(khv.x));
            float2 k1b = __half22float2(u2h(khv.y));
            uint2 th;
            th.x = h2u(__floats2half2_rn(z0.x + hdt * f.x, z0.y + hdt * f.y));
            th.y = h2u(__floats2half2_rn(z0.z + hdt * f.z, z0.w + hdt * f.w));
            ((uint2*)g_t2)[r4] = th;
            float4 ac;
            ac.x = z0.x + dt6 * k1a.x + dt3 * f.x;
            ac.y = z0.y + dt6 * k1a.y + dt3 * f.y;
            ac.z = z0.z + dt6 * k1b.x + dt3 * f.z;
            ac.w = z0.w + dt6 * k1b.y + dt3 * f.w;
            ((float4*)g_acc)[r4] = ac;
        } else if (stage == 3) {
            float4 z0 = ((const float4*)g_f0)[r4];
            uint2 th, kh;
            th.x = h2u(__floats2half2_rn(z0.x + dt * f.x, z0.y + dt * f.y));
            th.y = h2u(__floats2half2_rn(z0.z + dt * f.z, z0.w + dt * f.w));
            kh.x = h2u(__floats2half2_rn(f.x, f.y));
            kh.y = h2u(__floats2half2_rn(f.z, f.w));
            ((uint2*)g_t1)[r4] = th;
            ((uint2*)g_kh)[r4] = kh;
        } else {
            float4 ac = ((const float4*)g_acc)[r4];
            uint2 khv = ((const uint2*)g_kh)[r4];
            float2 k3a = __half22float2(u2h(khv.x));
            float2 k3b = __half22float2(u2h(khv.y));
            float4 zn;
            zn.x = ac.x + dt3 * k3a.x + dt6 * f.x;
            zn.y = ac.y + dt3 * k3a.y + dt6 * f.y;
            zn.z = ac.z + dt3 * k3b.x + dt6 * f.z;
            zn.w = ac.w + dt3 * k3b.y + dt6 * f.w;
            ((float4*)g_f0)[r4] = zn;
            uint2 hh;
            hh.x = h2u(__floats2half2_rn(zn.x, zn.y));
            hh.y = h2u(__floats2half2_rn(zn.z, zn.w));
            ((uint2*)g_h0)[r4] = hh;
            if (out != nullptr) ((float4*)out)[r4] = zn;
        }
    } else {
        // -------- general fallback (never taken for given inputs) --------
        __shared__ float s0[8], s1v[8], s_al[1];
        int w = t >> 5, l = t & 31;
        for (int rr = 0; rr < RPB; ++rr) {
            int r = blockIdx.x * RPB + rr;
            const float* zin = (stage == 1) ? g_w0 : (stage == 2) ? g_w1
                             : (stage == 3) ? g_w2 : g_w1;
            size_t ri = (size_t)r * DD + t;
            float zv = zin[ri];
            float d0 = zv * Wih[t];
            float d1 = zv * Wih[DD + t];
            #pragma unroll
            for (int off = 16; off; off >>= 1) {
                d0 += __shfl_down_sync(0xffffffffu, d0, off);
                d1 += __shfl_down_sync(0xffffffffu, d1, off);
            }
            if (l == 0) { s0[w] = d0; s1v[w] = d1; }
            __syncthreads();
            if (t == 0) {
                float a0 = 0.0f, a1 = 0.0f;
                #pragma unroll
                for (int i = 0; i < 8; ++i) { a0 += s0[i]; a1 += s1v[i]; }
                a0 = tanhf(a0 + g_hb[2 * r]);
                a1 = tanhf(a1 + g_hb[2 * r + 1]);
                float al = g_alpha[r] * a0 + a1;
                g_alpha[r] = al;
                s_al[0] = 1.0f / (1.0f + expf(-al));
            }
            int es = g_rowptr[r], ee = g_rowptr[r + 1];
            float az = 0.0f;
            for (int i = es; i < ee; ++i) {
                unsigned long long pk = g_edges[i];
                int   c = (int)(unsigned int)(pk & 0xffffffffu);
                float v = __uint_as_float((unsigned int)(pk >> 32));
                az += v * zin[(size_t)c * DD + t];
            }
            __syncthreads();
            float f = s_al[0] * 0.5f * (az - zv) + ((t < DH) ? x[(size_t)r * DH + t] : 0.0f);
            const float* zr = zin + (size_t)r * DD;
            for (int j = 0; j < DD; ++j) f += zr[j] * g_M[j * DD + t];

            if (stage == 1)      { g_wk[ri] = f;          g_w1[ri] = zv + hdt * f; }
            else if (stage == 2) { g_wk[ri] += 2.0f * f;  g_w2[ri] = g_w0[ri] + hdt * f; }
            else if (stage == 3) { g_wk[ri] += 2.0f * f;  g_w1[ri] = g_w0[ri] + dt * f; }
            else {
                float zn = g_w0[ri] + dt6 * (g_wk[ri] + f);
                g_w0[ri] = zn;
                if (out != nullptr && t < DH) out[(size_t)r * DH + t] = zn;
            }
            __syncthreads();
        }
    }
}

// ------------------- launch -------------------
extern "C" void kernel_launch(void* const* d_in, const int* in_sizes, int n_in,
                              void* d_out, int out_size) {
    const float* x      = (const float*)d_in[0];
    const int*   erows  = (const int*)  d_in[1];
    const int*   ecols  = (const int*)  d_in[2];
    const float* evals  = (const float*)d_in[3];
    const float* Wih    = (const float*)d_in[4];
    const float* Whh    = (const float*)d_in[5];
    const float* bih    = (const float*)d_in[6];
    const float* bhh    = (const float*)d_in[7];
    const float* h      = (const float*)d_in[8];
    const float* alpha0 = (const float*)d_in[9];
    const float* W      = (const float*)d_in[10];
    const float* dvec   = (const float*)d_in[11];
    float* out = (float*)d_out;

    reset_all<<<(NN + 255) / 256, 256>>>();
    computeM_small<<<DD + (NN + 255) / 256, 256>>>(W, dvec, alpha0, h, Whh, bih, bhh);
    count_k<<<(EE + 255) / 256, 256>>>(erows);
    scan_initz<<<NBLK + (NN * DH / 4 + SCAN_B - 1) / SCAN_B, SCAN_B>>>(x);
    scan_bsum<<<1, 128>>>();
    scan_add_zero<<<(NN + 255) / 256, 256>>>();
    scatter_k<<<(EE + 255) / 256, 256>>>(erows, ecols, evals);

    for (int s = 0; s < 2; ++s) {
        float* last_out = (s == 1) ? out : nullptr;
        ode_eval<<<NB8, 256>>>(1, x, Wih, nullptr);
        ode_eval<<<NB8, 256>>>(2, x, Wih, nullptr);
        ode_eval<<<NB8, 256>>>(3, x, Wih, nullptr);
        ode_eval<<<NB8, 256>>>(4, x, Wih, last_out);
    }
}

// round 6
// speedup vs baseline: 5.5621x; 1.2526x over previous
#include <cuda_runtime.h>
#include <cuda_fp16.h>
#include <math.h>

#define NN 100000
#define EE 800000
#define DH 128
#define DD 256
#define RPB 8             // rows per block = warps per block (fast path)
#define NB8 (NN / RPB)    // 12500
#define SCAN_B 1024
#define NBLK ((NN + SCAN_B - 1) / SCAN_B)   // 98

// bit-cast helpers (no intrinsic dependency)
__device__ __forceinline__ unsigned int h2u(__half2 h) {
    return *reinterpret_cast<unsigned int*>(&h);
}
__device__ __forceinline__ __half2 u2h(unsigned int u) {
    return *reinterpret_cast<__half2*>(&u);
}
__device__ __forceinline__ float4 u2f4(uint2 hv) {
    float2 a = __half22float2(u2h(hv.x));
    float2 b = __half22float2(u2h(hv.y));
    return make_float4(a.x, a.y, b.x, b.y);
}

// ------------- device-global scratch (no cudaMalloc allowed) -------------
// fast path
__device__ float  g_f0 [(size_t)NN * DH];   // z (fp32 carried state)
__device__ float  g_acc[(size_t)NN * DH];   // z + dt/6 k1 + dt/3 k2
__device__ __half g_h0 [(size_t)NN * DH];   // fp16 mirror of z
__device__ __half g_t1 [(size_t)NN * DH];   // t1 / t3 (fp16 only)
__device__ __half g_t2 [(size_t)NN * DH];   // t2 (fp16 only)
__device__ __half g_kh [(size_t)NN * DH];   // k1 / k3 (fp16)
__device__ __half g_xh [(size_t)NN * DH];   // fp16 mirror of x
// fallback (general M) buffers, layout [N,256]
__device__ float g_w0[(size_t)NN * DD];
__device__ float g_w1[(size_t)NN * DD];
__device__ float g_w2[(size_t)NN * DD];
__device__ float g_wk[(size_t)NN * DD];
__device__ float g_alpha[NN];
__device__ float g_hb[NN * 2];
__device__ float g_M[DD * DD];
__device__ int   g_mflag;
__device__ int   g_rowptr[NN + 1];
__device__ int   g_cnt[NN];
__device__ int   g_bsum[NBLK];
__device__ unsigned long long g_edges[EE]; // hi32 = val bits, lo32 = col

// ------------------- setup kernels -------------------
__global__ void reset_all() {
    int i = blockIdx.x * blockDim.x + threadIdx.x;
    if (i == 0) g_mflag = 0;
    if (i < NN) g_cnt[i] = 0;
}

__global__ void computeM_small(const float* __restrict__ W, const float* __restrict__ dvec,
                               const float* __restrict__ alpha0, const float* __restrict__ h,
                               const float* __restrict__ Whh, const float* __restrict__ bih,
                               const float* __restrict__ bhh) {
    if (blockIdx.x < DD) {
        int i = blockIdx.x, j = threadIdx.x;
        float s = 0.0f;
        for (int k = 0; k < DD; ++k) {
            float d = fminf(fmaxf(dvec[k], 0.0f), 1.0f);
            s += W[i * DD + k] * d * W[j * DD + k];
        }
        float m = s - ((i == j) ? 1.0f : 0.0f);
        g_M[i * DD + j] = m;
        if (m != 0.0f) atomicOr(&g_mflag, 1);
    } else {
        int i = (blockIdx.x - DD) * blockDim.x + threadIdx.x;
        if (i < NN) {
            g_alpha[i] = alpha0[i];
            float h0 = h[2 * i], h1 = h[2 * i + 1];
            g_hb[2 * i]     = h0 * Whh[0] + h1 * Whh[1] + bih[0] + bhh[0];
            g_hb[2 * i + 1] = h0 * Whh[2] + h1 * Whh[3] + bih[1] + bhh[1];
        }
    }
}

__global__ void count_k(const int* __restrict__ rows) {
    int i = blockIdx.x * blockDim.x + threadIdx.x;
    if (i < EE) atomicAdd(&g_cnt[rows[i]], 1);
}

// blocks [0,NBLK): local scan; blocks [NBLK, ...): vectorized z/x init
__global__ void scan_initz(const float* __restrict__ x) {
    if (blockIdx.x < NBLK) {
        __shared__ int buf[SCAN_B];
        int idx = blockIdx.x * SCAN_B + (int)threadIdx.x;
        int v = (idx < NN) ? g_cnt[idx] : 0;
        buf[threadIdx.x] = v;
        __syncthreads();
        for (int off = 1; off < SCAN_B; off <<= 1) {
            int tv = (threadIdx.x >= off) ? buf[threadIdx.x - off] : 0;
            __syncthreads();
            buf[threadIdx.x] += tv;
            __syncthreads();
        }
        if (idx < NN) g_rowptr[idx] = buf[threadIdx.x] - v;       // local exclusive
        if (threadIdx.x == SCAN_B - 1) g_bsum[blockIdx.x] = buf[SCAN_B - 1];
    } else {
        int i = (blockIdx.x - NBLK) * SCAN_B + (int)threadIdx.x;  // over NN*DH/4
        if (i < NN * DH / 4) {
            float4 v = ((const float4*)x)[i];
            uint2 hh;
            hh.x = h2u(__floats2half2_rn(v.x, v.y));
            hh.y = h2u(__floats2half2_rn(v.z, v.w));
            if (!g_mflag) {
                ((float4*)g_f0)[i] = v;
                ((uint2*)g_h0)[i] = hh;
                ((uint2*)g_xh)[i] = hh;
            } else {
                int r = i >> 5, c = (i & 31) * 4;
                float4* w = (float4*)(g_w0 + (size_t)r * DD);
                w[c / 4] = v;
                w[(DH + c) / 4] = make_float4(0.f, 0.f, 0.f, 0.f);
            }
        }
    }
}

__global__ void scan_bsum() {           // 1 block, 128 threads (NBLK <= 128)
    __shared__ int b[128];
    int v = ((int)threadIdx.x < NBLK) ? g_bsum[threadIdx.x] : 0;
    b[threadIdx.x] = v;
    __syncthreads();
    for (int off = 1; off < 128; off <<= 1) {
        int tv = (threadIdx.x >= off) ? b[threadIdx.x - off] : 0;
        __syncthreads();
        b[threadIdx.x] += tv;
        __syncthreads();
    }
    if ((int)threadIdx.x < NBLK) g_bsum[threadIdx.x] = b[threadIdx.x] - v;
    if (threadIdx.x == 127) g_rowptr[NN] = b[127];
}

__global__ void scan_add_zero() {
    int i = blockIdx.x * blockDim.x + threadIdx.x;
    if (i < NN) {
        g_rowptr[i] += g_bsum[i >> 10];
        g_cnt[i] = 0;
    }
}

__global__ void scatter_k(const int* __restrict__ rows, const int* __restrict__ cols,
                          const float* __restrict__ vals) {
    int i = blockIdx.x * blockDim.x + threadIdx.x;
    if (i < EE) {
        int r = rows[i];
        int pos = g_rowptr[r] + atomicAdd(&g_cnt[r], 1);
        g_edges[pos] = ((unsigned long long)__float_as_uint(vals[i]) << 32)
                       | (unsigned int)cols[i];
    }
}

// gather one edge into a 4-wide accumulator (lane covers cols 4*lane..4*lane+3)
__device__ __forceinline__ void edge_acc(const __half* zin, unsigned long long pk,
                                         int lane, float4& az) {
    int   c = (int)(unsigned int)(pk & 0xffffffffu);
    float v = __uint_as_float((unsigned int)(pk >> 32));
    uint2 hv = ((const uint2*)(zin + (size_t)c * DH))[lane];
    float2 a = __half22float2(u2h(hv.x));
    float2 b = __half22float2(u2h(hv.y));
    az.x += v * a.x; az.y += v * a.y; az.z += v * b.x; az.w += v * b.y;
}

// ------------------- fused ODE eval (one RK4 stage) -------------------
// Fast path: warp-per-row, 32 lanes x 4 cols, no shared memory / block sync.
__global__ __launch_bounds__(256) void ode_eval(int stage,
    const float* __restrict__ x, const float* __restrict__ Wih,
    float* __restrict__ out)
{
    const float hdt = 0.225f, dt = 0.45f, dt3 = 0.15f, dt6 = 0.075f;
    int t = threadIdx.x;

    if (!g_mflag) {
        int wrp = t >> 5, lane = t & 31;
        int r = blockIdx.x * RPB + wrp;
        const __half* zin = (stage == 1) ? g_h0 : (stage == 3) ? g_t2 : g_t1;
        size_t r4 = (size_t)r * (DH / 4) + lane;     // float4/uint2 index

        float4 zv = u2f4(((const uint2*)zin)[r4]);

        // gate dots -> all-lanes butterfly reduction
        float4 w0 = ((const float4*)Wih)[lane];
        float4 w1 = ((const float4*)(Wih + DD))[lane];
        float d0 = zv.x * w0.x + zv.y * w0.y + zv.z * w0.z + zv.w * w0.w;
        float d1 = zv.x * w1.x + zv.y * w1.y + zv.z * w1.z + zv.w * w1.w;
        #pragma unroll
        for (int off = 16; off; off >>= 1) {
            d0 += __shfl_xor_sync(0xffffffffu, d0, off);
            d1 += __shfl_xor_sync(0xffffffffu, d1, off);
        }
        float a0 = tanhf(d0 + g_hb[2 * r]);
        float a1 = tanhf(d1 + g_hb[2 * r + 1]);
        float al = g_alpha[r] * a0 + a1;          // all lanes redundantly
        if (lane == 0) g_alpha[r] = al;
        al = 1.0f / (1.0f + expf(-al));

        // SpMM gather, 4-deep software pipeline
        int es = g_rowptr[r], ee = g_rowptr[r + 1];
        float4 az = make_float4(0.f, 0.f, 0.f, 0.f);
        int i = es;
        for (; i + 4 <= ee; i += 4) {
            unsigned long long p0 = g_edges[i],     p1 = g_edges[i + 1];
            unsigned long long p2 = g_edges[i + 2], p3 = g_edges[i + 3];
            edge_acc(zin, p0, lane, az);
            edge_acc(zin, p1, lane, az);
            edge_acc(zin, p2, lane, az);
            edge_acc(zin, p3, lane, az);
        }
        for (; i < ee; ++i) edge_acc(zin, g_edges[i], lane, az);

        float4 x4 = u2f4(((const uint2*)g_xh)[r4]);
        float4 f;
        f.x = al * 0.5f * (az.x - zv.x) + x4.x;
        f.y = al * 0.5f * (az.y - zv.y) + x4.y;
        f.z = al * 0.5f * (az.z - zv.z) + x4.z;
        f.w = al * 0.5f * (az.w - zv.w) + x4.w;

        if (stage == 1) {
            uint2 th, kh;
            th.x = h2u(__floats2half2_rn(zv.x + hdt * f.x, zv.y + hdt * f.y));
            th.y = h2u(__floats2half2_rn(zv.z + hdt * f.z, zv.w + hdt * f.w));
            kh.x = h2u(__floats2half2_rn(f.x, f.y));
            kh.y = h2u(__floats2half2_rn(f.z, f.w));
            ((uint2*)g_t1)[r4] = th;
            ((uint2*)g_kh)[r4] = kh;
        } else if (stage == 2) {
            float4 z0 = ((const float4*)g_f0)[r4];
            uint2 khv = ((const uint2*)g_kh)[r4];
            float2 k1a = __half22float2(u2h(khv.x));
            float2 k1b = __half22float2(u2h(khv.y));
            uint2 th;
            th.x = h2u(__floats2half2_rn(z0.x + hdt * f.x, z0.y + hdt * f.y));
            th.y = h2u(__floats2half2_rn(z0.z + hdt * f.z, z0.w + hdt * f.w));
            ((uint2*)g_t2)[r4] = th;
            float4 ac;
            ac.x = z0.x + dt6 * k1a.x + dt3 * f.x;
            ac.y = z0.y + dt6 * k1a.y + dt3 * f.y;
            ac.z = z0.z + dt6 * k1b.x + dt3 * f.z;
            ac.w = z0.w + dt6 * k1b.y + dt3 * f.w;
            ((float4*)g_acc)[r4] = ac;
        } else if (stage == 3) {
            float4 z0 = u2f4(((const uint2*)g_h0)[r4]);   // fp16 z (t1 is fp16 anyway)
            uint2 th, kh;
            th.x = h2u(__floats2half2_rn(z0.x + dt * f.x, z0.y + dt * f.y));
            th.y = h2u(__floats2half2_rn(z0.z + dt * f.z, z0.w + dt * f.w));
            kh.x = h2u(__floats2half2_rn(f.x, f.y));
            kh.y = h2u(__floats2half2_rn(f.z, f.w));
            ((uint2*)g_t1)[r4] = th;
            ((uint2*)g_kh)[r4] = kh;
        } else {
            float4 ac = ((const float4*)g_acc)[r4];
            uint2 khv = ((const uint2*)g_kh)[r4];
            float2 k3a = __half22float2(u2h(khv.x));
            float2 k3b = __half22float2(u2h(khv.y));
            float4 zn;
            zn.x = ac.x + dt3 * k3a.x + dt6 * f.x;
            zn.y = ac.y + dt3 * k3a.y + dt6 * f.y;
            zn.z = ac.z + dt3 * k3b.x + dt6 * f.z;
            zn.w = ac.w + dt3 * k3b.y + dt6 * f.w;
            if (out != nullptr) {
                ((float4*)out)[r4] = zn;           // final eval: mirror writes are dead
            } else {
                ((float4*)g_f0)[r4] = zn;
                uint2 hh;
                hh.x = h2u(__floats2half2_rn(zn.x, zn.y));
                hh.y = h2u(__floats2half2_rn(zn.z, zn.w));
                ((uint2*)g_h0)[r4] = hh;
            }
        }
    } else {
        // -------- general fallback (never taken for given inputs) --------
        __shared__ float s0[8], s1v[8], s_al[1];
        int w = t >> 5, l = t & 31;
        for (int rr = 0; rr < RPB; ++rr) {
            int r = blockIdx.x * RPB + rr;
            const float* zin = (stage == 1) ? g_w0 : (stage == 2) ? g_w1
                             : (stage == 3) ? g_w2 : g_w1;
            size_t ri = (size_t)r * DD + t;
            float zv = zin[ri];
            float d0 = zv * Wih[t];
            float d1 = zv * Wih[DD + t];
            #pragma unroll
            for (int off = 16; off; off >>= 1) {
                d0 += __shfl_down_sync(0xffffffffu, d0, off);
                d1 += __shfl_down_sync(0xffffffffu, d1, off);
            }
            if (l == 0) { s0[w] = d0; s1v[w] = d1; }
            __syncthreads();
            if (t == 0) {
                float a0 = 0.0f, a1 = 0.0f;
                #pragma unroll
                for (int i = 0; i < 8; ++i) { a0 += s0[i]; a1 += s1v[i]; }
                a0 = tanhf(a0 + g_hb[2 * r]);
                a1 = tanhf(a1 + g_hb[2 * r + 1]);
                float al = g_alpha[r] * a0 + a1;
                g_alpha[r] = al;
                s_al[0] = 1.0f / (1.0f + expf(-al));
            }
            int es = g_rowptr[r], ee = g_rowptr[r + 1];
            float az = 0.0f;
            for (int i = es; i < ee; ++i) {
                unsigned long long pk = g_edges[i];
                int   c = (int)(unsigned int)(pk & 0xffffffffu);
                float v = __uint_as_float((unsigned int)(pk >> 32));
                az += v * zin[(size_t)c * DD + t];
            }
            __syncthreads();
            const float hdtF = 0.225f, dtF = 0.45f, dt6F = 0.075f;
            float f = s_al[0] * 0.5f * (az - zv) + ((t < DH) ? x[(size_t)r * DH + t] : 0.0f);
            const float* zr = zin + (size_t)r * DD;
            for (int j = 0; j < DD; ++j) f += zr[j] * g_M[j * DD + t];

            if (stage == 1)      { g_wk[ri] = f;          g_w1[ri] = zv + hdtF * f; }
            else if (stage == 2) { g_wk[ri] += 2.0f * f;  g_w2[ri] = g_w0[ri] + hdtF * f; }
            else if (stage == 3) { g_wk[ri] += 2.0f * f;  g_w1[ri] = g_w0[ri] + dtF * f; }
            else {
                float zn = g_w0[ri] + dt6F * (g_wk[ri] + f);
                g_w0[ri] = zn;
                if (out != nullptr && t < DH) out[(size_t)r * DH + t] = zn;
            }
            __syncthreads();
        }
    }
}

// ------------------- launch -------------------
extern "C" void kernel_launch(void* const* d_in, const int* in_sizes, int n_in,
                              void* d_out, int out_size) {
    const float* x      = (const float*)d_in[0];
    const int*   erows  = (const int*)  d_in[1];
    const int*   ecols  = (const int*)  d_in[2];
    const float* evals  = (const float*)d_in[3];
    const float* Wih    = (const float*)d_in[4];
    const float* Whh    = (const float*)d_in[5];
    const float* bih    = (const float*)d_in[6];
    const float* bhh    = (const float*)d_in[7];
    const float* h      = (const float*)d_in[8];
    const float* alpha0 = (const float*)d_in[9];
    const float* W      = (const float*)d_in[10];
    const float* dvec   = (const float*)d_in[11];
    float* out = (float*)d_out;

    reset_all<<<(NN + 255) / 256, 256>>>();
    computeM_small<<<DD + (NN + 255) / 256, 256>>>(W, dvec, alpha0, h, Whh, bih, bhh);
    count_k<<<(EE + 255) / 256, 256>>>(erows);
    scan_initz<<<NBLK + (NN * DH / 4 + SCAN_B - 1) / SCAN_B, SCAN_B>>>(x);
    scan_bsum<<<1, 128>>>();
    scan_add_zero<<<(NN + 255) / 256, 256>>>();
    scatter_k<<<(EE + 255) / 256, 256>>>(erows, ecols, evals);

    for (int s = 0; s < 2; ++s) {
        float* last_out = (s == 1) ? out : nullptr;
        ode_eval<<<NB8, 256>>>(1, x, Wih, nullptr);
        ode_eval<<<NB8, 256>>>(2, x, Wih, nullptr);
        ode_eval<<<NB8, 256>>>(3, x, Wih, nullptr);
        ode_eval<<<NB8, 256>>>(4, x, Wih, last_out);
    }
}

// round 7
// speedup vs baseline: 5.6579x; 1.0172x over previous
#include <cuda_runtime.h>
#include <cuda_fp16.h>
#include <math.h>

#define NN 100000
#define EE 800000
#define DH 128
#define DD 256
#define RPB 8             // rows per block = warps per block (fast path)
#define NB8 (NN / RPB)    // 12500
#define SCAN_B 1024
#define NBLK ((NN + SCAN_B - 1) / SCAN_B)   // 98

// bit-cast helpers (no intrinsic dependency)
__device__ __forceinline__ unsigned int h2u(__half2 h) {
    return *reinterpret_cast<unsigned int*>(&h);
}
__device__ __forceinline__ __half2 u2h(unsigned int u) {
    return *reinterpret_cast<__half2*>(&u);
}
__device__ __forceinline__ float4 u2f4(uint2 hv) {
    float2 a = __half22float2(u2h(hv.x));
    float2 b = __half22float2(u2h(hv.y));
    return make_float4(a.x, a.y, b.x, b.y);
}
__device__ __forceinline__ uint2 f42u(float4 v) {
    uint2 r;
    r.x = h2u(__floats2half2_rn(v.x, v.y));
    r.y = h2u(__floats2half2_rn(v.z, v.w));
    return r;
}

// ------------- device-global scratch (no cudaMalloc allowed) -------------
// fast path (all [N,128])
__device__ float  g_acc[(size_t)NN * DH];   // z + dt/6 k1 + dt/3 k2  (fp32)
__device__ __half g_h0 [(size_t)NN * DH];   // z high half (fp16, also gather mirror)
__device__ __half g_zl [(size_t)NN * DH];   // z residual (fp16): z ~= h0 + zl
__device__ __half g_t1 [(size_t)NN * DH];   // t1 / t3 (fp16)
__device__ __half g_t2 [(size_t)NN * DH];   // t2 (fp16)
__device__ __half g_kh [(size_t)NN * DH];   // k3 (fp16)
__device__ __half g_xh [(size_t)NN * DH];   // fp16 mirror of x
// fallback (general M) buffers, layout [N,256]
__device__ float g_w0[(size_t)NN * DD];
__device__ float g_w1[(size_t)NN * DD];
__device__ float g_w2[(size_t)NN * DD];
__device__ float g_wk[(size_t)NN * DD];
__device__ float g_alpha[NN];
__device__ float g_hb[NN * 2];
__device__ float g_M[DD * DD];
__device__ int   g_mflag;
__device__ int   g_rowptr[NN + 1];
__device__ int   g_cnt[NN];
__device__ int   g_bsum[NBLK];
__device__ unsigned long long g_edges[EE]; // hi32 = val bits, lo32 = col

// ------------------- setup kernels -------------------
__global__ void reset_all() {
    int i = blockIdx.x * blockDim.x + threadIdx.x;
    if (i == 0) g_mflag = 0;
    if (i < NN) g_cnt[i] = 0;
}

__global__ void computeM_small(const float* __restrict__ W, const float* __restrict__ dvec,
                               const float* __restrict__ alpha0, const float* __restrict__ h,
                               const float* __restrict__ Whh, const float* __restrict__ bih,
                               const float* __restrict__ bhh) {
    if (blockIdx.x < DD) {
        int i = blockIdx.x, j = threadIdx.x;
        float s = 0.0f;
        for (int k = 0; k < DD; ++k) {
            float d = fminf(fmaxf(dvec[k], 0.0f), 1.0f);
            s += W[i * DD + k] * d * W[j * DD + k];
        }
        float m = s - ((i == j) ? 1.0f : 0.0f);
        g_M[i * DD + j] = m;
        if (m != 0.0f) atomicOr(&g_mflag, 1);
    } else {
        int i = (blockIdx.x - DD) * blockDim.x + threadIdx.x;
        if (i < NN) {
            g_alpha[i] = alpha0[i];
            float h0 = h[2 * i], h1 = h[2 * i + 1];
            g_hb[2 * i]     = h0 * Whh[0] + h1 * Whh[1] + bih[0] + bhh[0];
            g_hb[2 * i + 1] = h0 * Whh[2] + h1 * Whh[3] + bih[1] + bhh[1];
        }
    }
}

__global__ void count_k(const int* __restrict__ rows) {
    int i = blockIdx.x * blockDim.x + threadIdx.x;
    if (i < EE) atomicAdd(&g_cnt[rows[i]], 1);
}

// blocks [0,NBLK): local scan; blocks [NBLK, ...): vectorized z/x init
__global__ void scan_initz(const float* __restrict__ x) {
    if (blockIdx.x < NBLK) {
        __shared__ int buf[SCAN_B];
        int idx = blockIdx.x * SCAN_B + (int)threadIdx.x;
        int v = (idx < NN) ? g_cnt[idx] : 0;
        buf[threadIdx.x] = v;
        __syncthreads();
        for (int off = 1; off < SCAN_B; off <<= 1) {
            int tv = (threadIdx.x >= off) ? buf[threadIdx.x - off] : 0;
            __syncthreads();
            buf[threadIdx.x] += tv;
            __syncthreads();
        }
        if (idx < NN) g_rowptr[idx] = buf[threadIdx.x] - v;       // local exclusive
        if (threadIdx.x == SCAN_B - 1) g_bsum[blockIdx.x] = buf[SCAN_B - 1];
    } else {
        int i = (blockIdx.x - NBLK) * SCAN_B + (int)threadIdx.x;  // over NN*DH/4
        if (i < NN * DH / 4) {
            float4 v = ((const float4*)x)[i];
            if (!g_mflag) {
                uint2 hh = f42u(v);
                ((uint2*)g_h0)[i] = hh;
                ((uint2*)g_xh)[i] = hh;
                float4 h4 = u2f4(hh);
                float4 rl;
                rl.x = v.x - h4.x; rl.y = v.y - h4.y;
                rl.z = v.z - h4.z; rl.w = v.w - h4.w;
                ((uint2*)g_zl)[i] = f42u(rl);
            } else {
                int r = i >> 5, c = (i & 31) * 4;
                float4* w = (float4*)(g_w0 + (size_t)r * DD);
                w[c / 4] = v;
                w[(DH + c) / 4] = make_float4(0.f, 0.f, 0.f, 0.f);
            }
        }
    }
}

__global__ void scan_bsum() {           // 1 block, 128 threads (NBLK <= 128)
    __shared__ int b[128];
    int v = ((int)threadIdx.x < NBLK) ? g_bsum[threadIdx.x] : 0;
    b[threadIdx.x] = v;
    __syncthreads();
    for (int off = 1; off < 128; off <<= 1) {
        int tv = (threadIdx.x >= off) ? b[threadIdx.x - off] : 0;
        __syncthreads();
        b[threadIdx.x] += tv;
        __syncthreads();
    }
    if ((int)threadIdx.x < NBLK) g_bsum[threadIdx.x] = b[threadIdx.x] - v;
    if (threadIdx.x == 127) g_rowptr[NN] = b[127];
}

__global__ void scan_add_zero() {
    int i = blockIdx.x * blockDim.x + threadIdx.x;
    if (i < NN) {
        g_rowptr[i] += g_bsum[i >> 10];
        g_cnt[i] = 0;
    }
}

__global__ void scatter_k(const int* __restrict__ rows, const int* __restrict__ cols,
                          const float* __restrict__ vals) {
    int i = blockIdx.x * blockDim.x + threadIdx.x;
    if (i < EE) {
        int r = rows[i];
        int pos = g_rowptr[r] + atomicAdd(&g_cnt[r], 1);
        g_edges[pos] = ((unsigned long long)__float_as_uint(vals[i]) << 32)
                       | (unsigned int)cols[i];
    }
}

// gather one edge into a 4-wide accumulator (lane covers cols 4*lane..4*lane+3)
__device__ __forceinline__ void edge_acc(const __half* zin, unsigned long long pk,
                                         int lane, float4& az) {
    int   c = (int)(unsigned int)(pk & 0xffffffffu);
    float v = __uint_as_float((unsigned int)(pk >> 32));
    uint2 hv = ((const uint2*)(zin + (size_t)c * DH))[lane];
    float2 a = __half22float2(u2h(hv.x));
    float2 b = __half22float2(u2h(hv.y));
    az.x += v * a.x; az.y += v * a.y; az.z += v * b.x; az.w += v * b.y;
}

// ------------------- fused ODE eval (one RK4 stage) -------------------
// Fast path: warp-per-row, 32 lanes x 4 cols, no shared memory / block sync.
//   S1: gather h0;  t1 = z + hdt f1                         (z from h0, fp16 ok)
//   S2: gather t1;  k1 = (t1 - z0)/hdt; t2 = z0 + hdt f2; acc = z0 + dt6 k1 + dt3 f2
//   S3: gather t2;  t1 = z0 + dt f3; kh = f3                (z0 from h0)
//   S4: gather t1;  z' = acc + dt3 kh + dt6 f4  -> (h0, zl) or out
__global__ __launch_bounds__(256) void ode_eval(int stage,
    const float* __restrict__ x, const float* __restrict__ Wih,
    float* __restrict__ out)
{
    const float hdt = 0.225f, dt = 0.45f, dt3 = 0.15f, dt6 = 0.075f;
    int t = threadIdx.x;

    if (!g_mflag) {
        int wrp = t >> 5, lane = t & 31;
        int r = blockIdx.x * RPB + wrp;
        const __half* zin = (stage == 1) ? g_h0 : (stage == 3) ? g_t2 : g_t1;
        size_t r4 = (size_t)r * (DH / 4) + lane;     // float4/uint2 index

        float4 zv = u2f4(((const uint2*)zin)[r4]);

        // gate dots -> all-lanes butterfly reduction
        float4 w0 = ((const float4*)Wih)[lane];
        float4 w1 = ((const float4*)(Wih + DD))[lane];
        float d0 = zv.x * w0.x + zv.y * w0.y + zv.z * w0.z + zv.w * w0.w;
        float d1 = zv.x * w1.x + zv.y * w1.y + zv.z * w1.z + zv.w * w1.w;
        #pragma unroll
        for (int off = 16; off; off >>= 1) {
            d0 += __shfl_xor_sync(0xffffffffu, d0, off);
            d1 += __shfl_xor_sync(0xffffffffu, d1, off);
        }
        float a0 = tanhf(d0 + g_hb[2 * r]);
        float a1 = tanhf(d1 + g_hb[2 * r + 1]);
        float al = g_alpha[r] * a0 + a1;          // all lanes redundantly
        if (lane == 0) g_alpha[r] = al;
        al = 1.0f / (1.0f + expf(-al));

        // SpMM gather, 4-deep software pipeline
        int es = g_rowptr[r], ee = g_rowptr[r + 1];
        float4 az = make_float4(0.f, 0.f, 0.f, 0.f);
        int i = es;
        for (; i + 4 <= ee; i += 4) {
            unsigned long long p0 = g_edges[i],     p1 = g_edges[i + 1];
            unsigned long long p2 = g_edges[i + 2], p3 = g_edges[i + 3];
            edge_acc(zin, p0, lane, az);
            edge_acc(zin, p1, lane, az);
            edge_acc(zin, p2, lane, az);
            edge_acc(zin, p3, lane, az);
        }
        for (; i < ee; ++i) edge_acc(zin, g_edges[i], lane, az);

        float4 x4 = u2f4(((const uint2*)g_xh)[r4]);
        float4 f;
        f.x = al * 0.5f * (az.x - zv.x) + x4.x;
        f.y = al * 0.5f * (az.y - zv.y) + x4.y;
        f.z = al * 0.5f * (az.z - zv.z) + x4.z;
        f.w = al * 0.5f * (az.w - zv.w) + x4.w;

        if (stage == 1) {
            // zv == z (fp16 high); t1 = z + hdt*f
            float4 t1;
            t1.x = zv.x + hdt * f.x; t1.y = zv.y + hdt * f.y;
            t1.z = zv.z + hdt * f.z; t1.w = zv.w + hdt * f.w;
            ((uint2*)g_t1)[r4] = f42u(t1);
        } else if (stage == 2) {
            // reconstruct fp32 z0 = h0 + zl
            float4 zh = u2f4(((const uint2*)g_h0)[r4]);
            float4 zr = u2f4(((const uint2*)g_zl)[r4]);
            float4 z0;
            z0.x = zh.x + zr.x; z0.y = zh.y + zr.y;
            z0.z = zh.z + zr.z; z0.w = zh.w + zr.w;
            // k1 recovered from t1 (== zv) : k1 = (t1 - z0)/hdt
            const float ih = 1.0f / 0.225f;
            float4 k1;
            k1.x = (zv.x - z0.x) * ih; k1.y = (zv.y - z0.y) * ih;
            k1.z = (zv.z - z0.z) * ih; k1.w = (zv.w - z0.w) * ih;
            float4 t2;
            t2.x = z0.x + hdt * f.x; t2.y = z0.y + hdt * f.y;
            t2.z = z0.z + hdt * f.z; t2.w = z0.w + hdt * f.w;
            ((uint2*)g_t2)[r4] = f42u(t2);
            float4 ac;
            ac.x = z0.x + dt6 * k1.x + dt3 * f.x;
            ac.y = z0.y + dt6 * k1.y + dt3 * f.y;
            ac.z = z0.z + dt6 * k1.z + dt3 * f.z;
            ac.w = z0.w + dt6 * k1.w + dt3 * f.w;
            ((float4*)g_acc)[r4] = ac;
        } else if (stage == 3) {
            float4 z0 = u2f4(((const uint2*)g_h0)[r4]);   // fp16 z ok (t3 is fp16)
            float4 t3;
            t3.x = z0.x + dt * f.x; t3.y = z0.y + dt * f.y;
            t3.z = z0.z + dt * f.z; t3.w = z0.w + dt * f.w;
            ((uint2*)g_t1)[r4] = f42u(t3);
            ((uint2*)g_kh)[r4] = f42u(f);
        } else {
            float4 ac = ((const float4*)g_acc)[r4];
            uint2 khv = ((const uint2*)g_kh)[r4];
            float4 k3 = u2f4(khv);
            float4 zn;
            zn.x = ac.x + dt3 * k3.x + dt6 * f.x;
            zn.y = ac.y + dt3 * k3.y + dt6 * f.y;
            zn.z = ac.z + dt3 * k3.z + dt6 * f.z;
            zn.w = ac.w + dt3 * k3.w + dt6 * f.w;
            if (out != nullptr) {
                ((float4*)out)[r4] = zn;           // final eval
            } else {
                uint2 hh = f42u(zn);
                ((uint2*)g_h0)[r4] = hh;
                float4 h4 = u2f4(hh);
                float4 rl;
                rl.x = zn.x - h4.x; rl.y = zn.y - h4.y;
                rl.z = zn.z - h4.z; rl.w = zn.w - h4.w;
                ((uint2*)g_zl)[r4] = f42u(rl);
            }
        }
    } else {
        // -------- general fallback (never taken for given inputs) --------
        __shared__ float s0[8], s1v[8], s_al[1];
        int w = t >> 5, l = t & 31;
        for (int rr = 0; rr < RPB; ++rr) {
            int r = blockIdx.x * RPB + rr;
            const float* zin = (stage == 1) ? g_w0 : (stage == 2) ? g_w1
                             : (stage == 3) ? g_w2 : g_w1;
            size_t ri = (size_t)r * DD + t;
            float zv = zin[ri];
            float d0 = zv * Wih[t];
            float d1 = zv * Wih[DD + t];
            #pragma unroll
            for (int off = 16; off; off >>= 1) {
                d0 += __shfl_down_sync(0xffffffffu, d0, off);
                d1 += __shfl_down_sync(0xffffffffu, d1, off);
            }
            if (l == 0) { s0[w] = d0; s1v[w] = d1; }
            __syncthreads();
            if (t == 0) {
                float a0 = 0.0f, a1 = 0.0f;
                #pragma unroll
                for (int i = 0; i < 8; ++i) { a0 += s0[i]; a1 += s1v[i]; }
                a0 = tanhf(a0 + g_hb[2 * r]);
                a1 = tanhf(a1 + g_hb[2 * r + 1]);
                float al = g_alpha[r] * a0 + a1;
                g_alpha[r] = al;
                s_al[0] = 1.0f / (1.0f + expf(-al));
            }
            int es = g_rowptr[r], ee = g_rowptr[r + 1];
            float az = 0.0f;
            for (int i = es; i < ee; ++i) {
                unsigned long long pk = g_edges[i];
                int   c = (int)(unsigned int)(pk & 0xffffffffu);
                float v = __uint_as_float((unsigned int)(pk >> 32));
                az += v * zin[(size_t)c * DD + t];
            }
            __syncthreads();
            float f = s_al[0] * 0.5f * (az - zv) + ((t < DH) ? x[(size_t)r * DH + t] : 0.0f);
            const float* zr = zin + (size_t)r * DD;
            for (int j = 0; j < DD; ++j) f += zr[j] * g_M[j * DD + t];

            if (stage == 1)      { g_wk[ri] = f;          g_w1[ri] = zv + hdt * f; }
            else if (stage == 2) { g_wk[ri] += 2.0f * f;  g_w2[ri] = g_w0[ri] + hdt * f; }
            else if (stage == 3) { g_wk[ri] += 2.0f * f;  g_w1[ri] = g_w0[ri] + dt * f; }
            else {
                float zn = g_w0[ri] + dt6 * (g_wk[ri] + f);
                g_w0[ri] = zn;
                if (out != nullptr && t < DH) out[(size_t)r * DH + t] = zn;
            }
            __syncthreads();
        }
    }
}

// ------------------- launch -------------------
extern "C" void kernel_launch(void* const* d_in, const int* in_sizes, int n_in,
                              void* d_out, int out_size) {
    const float* x      = (const float*)d_in[0];
    const int*   erows  = (const int*)  d_in[1];
    const int*   ecols  = (const int*)  d_in[2];
    const float* evals  = (const float*)d_in[3];
    const float* Wih    = (const float*)d_in[4];
    const float* Whh    = (const float*)d_in[5];
    const float* bih    = (const float*)d_in[6];
    const float* bhh    = (const float*)d_in[7];
    const float* h      = (const float*)d_in[8];
    const float* alpha0 = (const float*)d_in[9];
    const float* W      = (const float*)d_in[10];
    const float* dvec   = (const float*)d_in[11];
    float* out = (float*)d_out;

    reset_all<<<(NN + 255) / 256, 256>>>();
    computeM_small<<<DD + (NN + 255) / 256, 256>>>(W, dvec, alpha0, h, Whh, bih, bhh);
    count_k<<<(EE + 255) / 256, 256>>>(erows);
    scan_initz<<<NBLK + (NN * DH / 4 + SCAN_B - 1) / SCAN_B, SCAN_B>>>(x);
    scan_bsum<<<1, 128>>>();
    scan_add_zero<<<(NN + 255) / 256, 256>>>();
    scatter_k<<<(EE + 255) / 256, 256>>>(erows, ecols, evals);

    for (int s = 0; s < 2; ++s) {
        float* last_out = (s == 1) ? out : nullptr;
        ode_eval<<<NB8, 256>>>(1, x, Wih, nullptr);
        ode_eval<<<NB8, 256>>>(2, x, Wih, nullptr);
        ode_eval<<<NB8, 256>>>(3, x, Wih, nullptr);
        ode_eval<<<NB8, 256>>>(4, x, Wih, last_out);
    }
}